// round 1
// baseline (speedup 1.0000x reference)
#include <cuda_runtime.h>
#include <math.h>

// ---------------------------------------------------------------------------
// GCNEncoder: x = relu(NF @ Wemb + b); 2x { Q,K proj; S=softmax(mask(QK^T/s));
//             C = S@X; C2 = C@Wc; X = LN(X + C2) }
// Shapes: B=32, N=1024, D=1024, D_FF=512, L=2. All GEMM dims % 128 == 0.
// ---------------------------------------------------------------------------

#define BM 128
#define BN 128
#define BK 16

static const int BB   = 32;
static const int NN_  = 1024;
static const int DD   = 1024;
static const int DFF  = 512;
static const long long MTOT = 32768; // B*N

// Scratch (device globals; no allocations allowed)
__device__ float g_X [32768ll * 1024];
__device__ float g_Q [32768ll * 512];
__device__ float g_K [32768ll * 512];
__device__ float g_S [32ll * 1024 * 1024];
__device__ float g_C [32768ll * 1024];
__device__ float g_C2[32768ll * 1024];

// ---------------------------------------------------------------------------
// Tiled fp32 GEMM. C = alpha * A(MxK) * B  (+bias) (+relu)
// TRANS_B=false: B is K x N row-major.  TRANS_B=true: B is N x K row-major.
// Batch via blockIdx.z with element strides sA/sB/sC.
// Requires: M%128==0, N%128==0, K%16==0 (guaranteed by problem shapes).
// ---------------------------------------------------------------------------
template <bool TRANS_B, bool RELU, bool BIAS>
__global__ void __launch_bounds__(256, 2)
gemm_kernel(const float* __restrict__ A, const float* __restrict__ B,
            const float* __restrict__ bias, float* __restrict__ C,
            int M, int N, int K,
            long long sA, long long sB, long long sC, float alpha)
{
    __shared__ float As[BK][BM];
    __shared__ float Bs[BK][BN];

    const int bz = blockIdx.z;
    A += (long long)bz * sA;
    B += (long long)bz * sB;
    C += (long long)bz * sC;

    const int tid = threadIdx.x;
    const int rowBase = blockIdx.y * BM;
    const int colBase = blockIdx.x * BN;
    const int tx = tid & 15;      // 0..15 (col group)
    const int ty = tid >> 4;      // 0..15 (row group)

    float acc[8][8];
#pragma unroll
    for (int i = 0; i < 8; i++)
#pragma unroll
        for (int j = 0; j < 8; j++) acc[i][j] = 0.f;

    for (int k0 = 0; k0 < K; k0 += BK) {
        // ---- load A tile (128 rows x 16 k), store transposed into As[k][m]
#pragma unroll
        for (int i = 0; i < 2; i++) {
            int idx = tid + i * 256;
            int r   = idx >> 2;          // 0..127
            int kc  = (idx & 3) * 4;     // 0,4,8,12
            float4 v = *(const float4*)&A[(long long)(rowBase + r) * K + k0 + kc];
            As[kc + 0][r] = v.x; As[kc + 1][r] = v.y;
            As[kc + 2][r] = v.z; As[kc + 3][r] = v.w;
        }
        // ---- load B tile
        if (!TRANS_B) {
            // B is K x N: tile 16 k-rows x 128 cols
#pragma unroll
            for (int i = 0; i < 2; i++) {
                int idx = tid + i * 256;
                int r   = idx >> 5;          // 0..15 (k)
                int c   = (idx & 31) * 4;    // 0..124
                float4 v = *(const float4*)&B[(long long)(k0 + r) * N + colBase + c];
                *(float4*)&Bs[r][c] = v;
            }
        } else {
            // B is N x K: tile 128 n-rows x 16 k, store transposed into Bs[k][n]
#pragma unroll
            for (int i = 0; i < 2; i++) {
                int idx = tid + i * 256;
                int r   = idx >> 2;          // 0..127 (n)
                int kc  = (idx & 3) * 4;     // 0,4,8,12
                float4 v = *(const float4*)&B[(long long)(colBase + r) * K + k0 + kc];
                Bs[kc + 0][r] = v.x; Bs[kc + 1][r] = v.y;
                Bs[kc + 2][r] = v.z; Bs[kc + 3][r] = v.w;
            }
        }
        __syncthreads();

#pragma unroll
        for (int kk = 0; kk < BK; kk++) {
            float a[8], b[8];
            *(float4*)&a[0] = *(const float4*)&As[kk][ty * 8];
            *(float4*)&a[4] = *(const float4*)&As[kk][ty * 8 + 4];
            *(float4*)&b[0] = *(const float4*)&Bs[kk][tx * 8];
            *(float4*)&b[4] = *(const float4*)&Bs[kk][tx * 8 + 4];
#pragma unroll
            for (int i = 0; i < 8; i++)
#pragma unroll
                for (int j = 0; j < 8; j++)
                    acc[i][j] += a[i] * b[j];
        }
        __syncthreads();
    }

    // ---- epilogue
    float bvals[8];
    if (BIAS) {
#pragma unroll
        for (int j = 0; j < 8; j++) bvals[j] = bias[colBase + tx * 8 + j];
    }
#pragma unroll
    for (int i = 0; i < 8; i++) {
        long long r = rowBase + ty * 8 + i;
        float* crow = &C[r * (long long)N + colBase + tx * 8];
#pragma unroll
        for (int j0 = 0; j0 < 8; j0 += 4) {
            float4 v;
            v.x = acc[i][j0 + 0] * alpha;
            v.y = acc[i][j0 + 1] * alpha;
            v.z = acc[i][j0 + 2] * alpha;
            v.w = acc[i][j0 + 3] * alpha;
            if (BIAS) {
                v.x += bvals[j0 + 0]; v.y += bvals[j0 + 1];
                v.z += bvals[j0 + 2]; v.w += bvals[j0 + 3];
            }
            if (RELU) {
                v.x = fmaxf(v.x, 0.f); v.y = fmaxf(v.y, 0.f);
                v.z = fmaxf(v.z, 0.f); v.w = fmaxf(v.w, 0.f);
            }
            *(float4*)&crow[j0] = v;
        }
    }
}

// ---------------------------------------------------------------------------
// Block-wide reduction helpers (blockDim.x == 256)
// ---------------------------------------------------------------------------
__device__ __forceinline__ float block_reduce_max(float v, float* red) {
    int lane = threadIdx.x & 31, wid = threadIdx.x >> 5;
#pragma unroll
    for (int o = 16; o > 0; o >>= 1) v = fmaxf(v, __shfl_xor_sync(0xffffffffu, v, o));
    if (lane == 0) red[wid] = v;
    __syncthreads();
    if (wid == 0) {
        float x = (lane < 8) ? red[lane] : -INFINITY;
#pragma unroll
        for (int o = 4; o > 0; o >>= 1) x = fmaxf(x, __shfl_xor_sync(0xffffffffu, x, o));
        if (lane == 0) red[0] = x;
    }
    __syncthreads();
    float r = red[0];
    __syncthreads();
    return r;
}

__device__ __forceinline__ float block_reduce_sum(float v, float* red) {
    int lane = threadIdx.x & 31, wid = threadIdx.x >> 5;
#pragma unroll
    for (int o = 16; o > 0; o >>= 1) v += __shfl_xor_sync(0xffffffffu, v, o);
    if (lane == 0) red[wid] = v;
    __syncthreads();
    if (wid == 0) {
        float x = (lane < 8) ? red[lane] : 0.f;
#pragma unroll
        for (int o = 4; o > 0; o >>= 1) x += __shfl_xor_sync(0xffffffffu, x, o);
        if (lane == 0) red[0] = x;
    }
    __syncthreads();
    float r = red[0];
    __syncthreads();
    return r;
}

// ---------------------------------------------------------------------------
// Masked softmax over each 1024-wide row of S (in place). mask = (rel == 0)
// where(mask, -inf) -> softmax -> where(mask, 0)
// ---------------------------------------------------------------------------
__global__ void __launch_bounds__(256)
softmax_mask_kernel(float* __restrict__ S, const float* __restrict__ rel)
{
    __shared__ float red[8];
    long long row = blockIdx.x;
    float* s = S + row * 1024;
    const float* r = rel + row * 1024;
    int tid = threadIdx.x;

    float4 sv = *(const float4*)&s[tid * 4];
    float4 mv = *(const float4*)&r[tid * 4];
    float v0 = (mv.x != 0.f) ? sv.x : -INFINITY;
    float v1 = (mv.y != 0.f) ? sv.y : -INFINITY;
    float v2 = (mv.z != 0.f) ? sv.z : -INFINITY;
    float v3 = (mv.w != 0.f) ? sv.w : -INFINITY;

    float vmax = block_reduce_max(fmaxf(fmaxf(v0, v1), fmaxf(v2, v3)), red);

    float e0 = (mv.x != 0.f) ? expf(v0 - vmax) : 0.f;
    float e1 = (mv.y != 0.f) ? expf(v1 - vmax) : 0.f;
    float e2 = (mv.z != 0.f) ? expf(v2 - vmax) : 0.f;
    float e3 = (mv.w != 0.f) ? expf(v3 - vmax) : 0.f;

    float sum = block_reduce_sum(e0 + e1 + e2 + e3, red);
    float inv = (sum > 0.f) ? (1.f / sum) : 0.f;

    float4 o; o.x = e0 * inv; o.y = e1 * inv; o.z = e2 * inv; o.w = e3 * inv;
    *(float4*)&s[tid * 4] = o;
}

// ---------------------------------------------------------------------------
// out[row] = LayerNorm(X[row] + Cx[row]) * g + b   (row length 1024)
// var = E[x^2] - E[x]^2 (biased, matching jnp.var), eps = 1e-5
// ---------------------------------------------------------------------------
__global__ void __launch_bounds__(256)
add_ln_kernel(const float* __restrict__ X, const float* __restrict__ Cx,
              const float* __restrict__ g, const float* __restrict__ b,
              float* __restrict__ out)
{
    __shared__ float red[8];
    long long row = blockIdx.x;
    int tid = threadIdx.x;

    float4 xv = *(const float4*)&X [row * 1024 + tid * 4];
    float4 cv = *(const float4*)&Cx[row * 1024 + tid * 4];
    float v0 = xv.x + cv.x, v1 = xv.y + cv.y, v2 = xv.z + cv.z, v3 = xv.w + cv.w;

    float sum  = block_reduce_sum(v0 + v1 + v2 + v3, red);
    float ssq  = block_reduce_sum(v0 * v0 + v1 * v1 + v2 * v2 + v3 * v3, red);
    float mean = sum * (1.f / 1024.f);
    float var  = ssq * (1.f / 1024.f) - mean * mean;
    float rstd = rsqrtf(var + 1e-5f);

    float4 gv = *(const float4*)&g[tid * 4];
    float4 bv = *(const float4*)&b[tid * 4];
    float4 o;
    o.x = (v0 - mean) * rstd * gv.x + bv.x;
    o.y = (v1 - mean) * rstd * gv.y + bv.y;
    o.z = (v2 - mean) * rstd * gv.z + bv.z;
    o.w = (v3 - mean) * rstd * gv.w + bv.w;
    *(float4*)&out[row * 1024 + tid * 4] = o;
}

// ---------------------------------------------------------------------------
extern "C" void kernel_launch(void* const* d_in, const int* in_sizes, int n_in,
                              void* d_out, int out_size)
{
    const float* node_fts = (const float*)d_in[0];   // (32,1024,1024)
    const float* rel      = (const float*)d_in[1];   // (32,1024,1024)
    const float* W_emb    = (const float*)d_in[2];   // (1024,1024)
    const float* b_emb    = (const float*)d_in[3];   // (1024)
    const float* Wq       = (const float*)d_in[4];   // (2,1024,512)
    const float* bq       = (const float*)d_in[5];   // (2,512)
    const float* Wk       = (const float*)d_in[6];   // (2,1024,512)
    const float* bk       = (const float*)d_in[7];   // (2,512)
    const float* Wc       = (const float*)d_in[8];   // (2,1024,1024)
    const float* ln_g     = (const float*)d_in[9];   // (2,1024)
    const float* ln_b     = (const float*)d_in[10];  // (2,1024)
    float* out = (float*)d_out;                      // (32,1024,1024)

    float *X, *Q, *K, *S, *C, *C2;
    cudaGetSymbolAddress((void**)&X,  g_X);
    cudaGetSymbolAddress((void**)&Q,  g_Q);
    cudaGetSymbolAddress((void**)&K,  g_K);
    cudaGetSymbolAddress((void**)&S,  g_S);
    cudaGetSymbolAddress((void**)&C,  g_C);
    cudaGetSymbolAddress((void**)&C2, g_C2);

    dim3 blk(256);
    const float inv_sqrt_dff = 1.0f / sqrtf((float)DFF);

    // Embedding: X = relu(NF @ W_emb + b_emb)    [32768 x 1024 x 1024]
    gemm_kernel<false, true, true>
        <<<dim3(DD / BN, (int)(MTOT / BM), 1), blk>>>(
            node_fts, W_emb, b_emb, X, (int)MTOT, DD, DD, 0, 0, 0, 1.0f);

    for (int l = 0; l < 2; l++) {
        const float* Wql = Wq + (long long)l * DD * DFF;
        const float* bql = bq + (long long)l * DFF;
        const float* Wkl = Wk + (long long)l * DD * DFF;
        const float* bkl = bk + (long long)l * DFF;
        const float* Wcl = Wc + (long long)l * DD * DD;
        const float* gl  = ln_g + (long long)l * DD;
        const float* bl  = ln_b + (long long)l * DD;

        // Q = X @ Wq + bq ; K = X @ Wk + bk     [32768 x 512 x 1024]
        gemm_kernel<false, false, true>
            <<<dim3(DFF / BN, (int)(MTOT / BM), 1), blk>>>(
                X, Wql, bql, Q, (int)MTOT, DFF, DD, 0, 0, 0, 1.0f);
        gemm_kernel<false, false, true>
            <<<dim3(DFF / BN, (int)(MTOT / BM), 1), blk>>>(
                X, Wkl, bkl, K, (int)MTOT, DFF, DD, 0, 0, 0, 1.0f);

        // S = (Q @ K^T) / sqrt(DFF)             [32 x (1024 x 1024 x 512)]
        gemm_kernel<true, false, false>
            <<<dim3(NN_ / BN, NN_ / BM, BB), blk>>>(
                Q, K, nullptr, S, NN_, NN_, DFF,
                (long long)NN_ * DFF, (long long)NN_ * DFF,
                (long long)NN_ * NN_, inv_sqrt_dff);

        // masked softmax over rows of S
        softmax_mask_kernel<<<(int)MTOT, blk>>>(S, rel);

        // C = S @ X                              [32 x (1024 x 1024 x 1024)]
        gemm_kernel<false, false, false>
            <<<dim3(DD / BN, NN_ / BM, BB), blk>>>(
                S, X, nullptr, C, NN_, DD, NN_,
                (long long)NN_ * NN_, (long long)NN_ * DD,
                (long long)NN_ * DD, 1.0f);

        // C2 = C @ Wc                            [32768 x 1024 x 1024]
        gemm_kernel<false, false, false>
            <<<dim3(DD / BN, (int)(MTOT / BM), 1), blk>>>(
                C, Wcl, nullptr, C2, (int)MTOT, DD, DD, 0, 0, 0, 1.0f);

        // X = LN(X + C2) * g + b   (last layer writes d_out)
        float* dst = (l == 1) ? out : X;
        add_ln_kernel<<<(int)MTOT, blk>>>(X, C2, gl, bl, dst);
    }
}

// round 2
// speedup vs baseline: 2.8061x; 2.8061x over previous
#include <cuda_runtime.h>
#include <math.h>
#include <stdint.h>

// ---------------------------------------------------------------------------
// GCNEncoder on tensor cores (tf32 mma.sync), fp32 accumulate.
// Shapes: B=32, N=1024, D=1024, D_FF=512, L=2. All GEMM dims % 128 == 0.
// ---------------------------------------------------------------------------

#define BM 128
#define BN 128
#define BK 32
#define AS_STRIDE 36    // BK + 4  (A stored [m][k])
#define BS_STRIDE 136   // BN + 8  (B stored [k][n])

static const int BB   = 32;
static const int NN_  = 1024;
static const int DD   = 1024;
static const int DFF  = 512;
static const long long MTOT = 32768; // B*N

// Scratch (device globals; no allocations allowed)
__device__ float g_X [32768ll * 1024];
__device__ float g_Q [32768ll * 512];
__device__ float g_K [32768ll * 512];
__device__ float g_S [32ll * 1024 * 1024];
__device__ float g_C [32768ll * 1024];
__device__ float g_C2[32768ll * 1024];

__device__ __forceinline__ uint32_t f2tf32(float x) {
    uint32_t t;
    asm("cvt.rna.tf32.f32 %0, %1;" : "=r"(t) : "f"(x));
    return t;
}

__device__ __forceinline__ void mma_tf32(float c[4], const uint32_t a[4],
                                         const uint32_t b[2]) {
    asm volatile(
        "mma.sync.aligned.m16n8k8.row.col.f32.tf32.tf32.f32 "
        "{%0,%1,%2,%3}, {%4,%5,%6,%7}, {%8,%9}, {%0,%1,%2,%3};\n"
        : "+f"(c[0]), "+f"(c[1]), "+f"(c[2]), "+f"(c[3])
        : "r"(a[0]), "r"(a[1]), "r"(a[2]), "r"(a[3]),
          "r"(b[0]), "r"(b[1]));
}

// ---------------------------------------------------------------------------
// Tensor-core GEMM. C = alpha * A(MxK) * B  (+bias) (+relu)
// TRANS_B=false: B is K x N row-major.  TRANS_B=true: B is N x K row-major.
// Batch via blockIdx.z with element strides sA/sB/sC.
// Requires: M%128==0, N%128==0, K%32==0.
// 256 threads = 8 warps as 2(m) x 4(n); warp tile 64x32; 4x4 m16n8k8 frags.
// ---------------------------------------------------------------------------
template <bool TRANS_B, bool RELU, bool BIAS>
__global__ void __launch_bounds__(256, 2)
gemm_tc(const float* __restrict__ A, const float* __restrict__ B,
        const float* __restrict__ bias, float* __restrict__ C,
        int M, int N, int K,
        long long sA, long long sB, long long sC, float alpha)
{
    __shared__ uint32_t As[BM * AS_STRIDE];   // [m][k], tf32 bits
    __shared__ uint32_t Bs[BK * BS_STRIDE];   // [k][n], tf32 bits

    const int bz = blockIdx.z;
    A += (long long)bz * sA;
    B += (long long)bz * sB;
    C += (long long)bz * sC;

    const int tid  = threadIdx.x;
    const int lane = tid & 31;
    const int wid  = tid >> 5;
    const int warpM = wid >> 2;  // 0..1
    const int warpN = wid & 3;   // 0..3
    const int rowBase = blockIdx.y * BM;
    const int colBase = blockIdx.x * BN;

    float acc[4][4][4];
#pragma unroll
    for (int i = 0; i < 4; i++)
#pragma unroll
        for (int j = 0; j < 4; j++)
#pragma unroll
            for (int r = 0; r < 4; r++) acc[i][j][r] = 0.f;

    const int lq = lane >> 2;   // 0..7
    const int lr = lane & 3;    // 0..3

    for (int k0 = 0; k0 < K; k0 += BK) {
        // ---- A tile: 128 x 32, row-major copy, tf32-convert
#pragma unroll
        for (int i = 0; i < 4; i++) {
            int gid = tid + i * 256;
            int r = gid >> 3;              // 0..127
            int c = (gid & 7) * 4;         // 0..28
            float4 v = *(const float4*)&A[(long long)(rowBase + r) * K + k0 + c];
            uint32_t* dst = &As[r * AS_STRIDE + c];
            dst[0] = f2tf32(v.x); dst[1] = f2tf32(v.y);
            dst[2] = f2tf32(v.z); dst[3] = f2tf32(v.w);
        }
        // ---- B tile -> Bs[k][n]
        if (!TRANS_B) {
#pragma unroll
            for (int i = 0; i < 4; i++) {
                int gid = tid + i * 256;
                int r = gid >> 5;          // 0..31 (k)
                int c = (gid & 31) * 4;    // 0..124 (n)
                float4 v = *(const float4*)&B[(long long)(k0 + r) * N + colBase + c];
                uint32_t* dst = &Bs[r * BS_STRIDE + c];
                dst[0] = f2tf32(v.x); dst[1] = f2tf32(v.y);
                dst[2] = f2tf32(v.z); dst[3] = f2tf32(v.w);
            }
        } else {
            // B is N x K: transpose during store
#pragma unroll
            for (int i = 0; i < 4; i++) {
                int gid = tid + i * 256;
                int n = gid >> 3;          // 0..127
                int kq = (gid & 7) * 4;    // 0..28
                float4 v = *(const float4*)&B[(long long)(colBase + n) * K + k0 + kq];
                Bs[(kq + 0) * BS_STRIDE + n] = f2tf32(v.x);
                Bs[(kq + 1) * BS_STRIDE + n] = f2tf32(v.y);
                Bs[(kq + 2) * BS_STRIDE + n] = f2tf32(v.z);
                Bs[(kq + 3) * BS_STRIDE + n] = f2tf32(v.w);
            }
        }
        __syncthreads();

#pragma unroll
        for (int ks = 0; ks < 4; ks++) {
            const int kb = ks * 8;
            uint32_t afr[4][4];
#pragma unroll
            for (int i = 0; i < 4; i++) {
                int base = (warpM * 64 + i * 16 + lq) * AS_STRIDE + kb + lr;
                afr[i][0] = As[base];
                afr[i][1] = As[base + 8 * AS_STRIDE];
                afr[i][2] = As[base + 4];
                afr[i][3] = As[base + 8 * AS_STRIDE + 4];
            }
            uint32_t bfr[4][2];
#pragma unroll
            for (int j = 0; j < 4; j++) {
                int bcol = warpN * 32 + j * 8 + lq;
                bfr[j][0] = Bs[(kb + lr) * BS_STRIDE + bcol];
                bfr[j][1] = Bs[(kb + lr + 4) * BS_STRIDE + bcol];
            }
#pragma unroll
            for (int i = 0; i < 4; i++)
#pragma unroll
                for (int j = 0; j < 4; j++)
                    mma_tf32(acc[i][j], afr[i], bfr[j]);
        }
        __syncthreads();
    }

    // ---- epilogue
#pragma unroll
    for (int i = 0; i < 4; i++) {
        int row0 = rowBase + warpM * 64 + i * 16 + lq;
#pragma unroll
        for (int j = 0; j < 4; j++) {
            int col = colBase + warpN * 32 + j * 8 + lr * 2;
            float b0 = 0.f, b1 = 0.f;
            if (BIAS) { b0 = bias[col]; b1 = bias[col + 1]; }
            float2 v;
            v.x = acc[i][j][0] * alpha + b0;
            v.y = acc[i][j][1] * alpha + b1;
            if (RELU) { v.x = fmaxf(v.x, 0.f); v.y = fmaxf(v.y, 0.f); }
            *(float2*)&C[(long long)row0 * N + col] = v;
            v.x = acc[i][j][2] * alpha + b0;
            v.y = acc[i][j][3] * alpha + b1;
            if (RELU) { v.x = fmaxf(v.x, 0.f); v.y = fmaxf(v.y, 0.f); }
            *(float2*)&C[(long long)(row0 + 8) * N + col] = v;
        }
    }
}

// ---------------------------------------------------------------------------
// Block-wide reduction helpers (blockDim.x == 256)
// ---------------------------------------------------------------------------
__device__ __forceinline__ float block_reduce_max(float v, float* red) {
    int lane = threadIdx.x & 31, wid = threadIdx.x >> 5;
#pragma unroll
    for (int o = 16; o > 0; o >>= 1) v = fmaxf(v, __shfl_xor_sync(0xffffffffu, v, o));
    if (lane == 0) red[wid] = v;
    __syncthreads();
    if (wid == 0) {
        float x = (lane < 8) ? red[lane] : -INFINITY;
#pragma unroll
        for (int o = 4; o > 0; o >>= 1) x = fmaxf(x, __shfl_xor_sync(0xffffffffu, x, o));
        if (lane == 0) red[0] = x;
    }
    __syncthreads();
    float r = red[0];
    __syncthreads();
    return r;
}

__device__ __forceinline__ float block_reduce_sum(float v, float* red) {
    int lane = threadIdx.x & 31, wid = threadIdx.x >> 5;
#pragma unroll
    for (int o = 16; o > 0; o >>= 1) v += __shfl_xor_sync(0xffffffffu, v, o);
    if (lane == 0) red[wid] = v;
    __syncthreads();
    if (wid == 0) {
        float x = (lane < 8) ? red[lane] : 0.f;
#pragma unroll
        for (int o = 4; o > 0; o >>= 1) x += __shfl_xor_sync(0xffffffffu, x, o);
        if (lane == 0) red[0] = x;
    }
    __syncthreads();
    float r = red[0];
    __syncthreads();
    return r;
}

// ---------------------------------------------------------------------------
// Masked softmax over each 1024-wide row of S (in place). mask = (rel == 0)
// ---------------------------------------------------------------------------
__global__ void __launch_bounds__(256)
softmax_mask_kernel(float* __restrict__ S, const float* __restrict__ rel)
{
    __shared__ float red[8];
    long long row = blockIdx.x;
    float* s = S + row * 1024;
    const float* r = rel + row * 1024;
    int tid = threadIdx.x;

    float4 sv = *(const float4*)&s[tid * 4];
    float4 mv = *(const float4*)&r[tid * 4];
    float v0 = (mv.x != 0.f) ? sv.x : -INFINITY;
    float v1 = (mv.y != 0.f) ? sv.y : -INFINITY;
    float v2 = (mv.z != 0.f) ? sv.z : -INFINITY;
    float v3 = (mv.w != 0.f) ? sv.w : -INFINITY;

    float vmax = block_reduce_max(fmaxf(fmaxf(v0, v1), fmaxf(v2, v3)), red);

    float e0 = (mv.x != 0.f) ? expf(v0 - vmax) : 0.f;
    float e1 = (mv.y != 0.f) ? expf(v1 - vmax) : 0.f;
    float e2 = (mv.z != 0.f) ? expf(v2 - vmax) : 0.f;
    float e3 = (mv.w != 0.f) ? expf(v3 - vmax) : 0.f;

    float sum = block_reduce_sum(e0 + e1 + e2 + e3, red);
    float inv = (sum > 0.f) ? (1.f / sum) : 0.f;

    float4 o; o.x = e0 * inv; o.y = e1 * inv; o.z = e2 * inv; o.w = e3 * inv;
    *(float4*)&s[tid * 4] = o;
}

// ---------------------------------------------------------------------------
// out[row] = LayerNorm(X[row] + Cx[row]) * g + b   (row length 1024)
// ---------------------------------------------------------------------------
__global__ void __launch_bounds__(256)
add_ln_kernel(const float* __restrict__ X, const float* __restrict__ Cx,
              const float* __restrict__ g, const float* __restrict__ b,
              float* __restrict__ out)
{
    __shared__ float red[8];
    long long row = blockIdx.x;
    int tid = threadIdx.x;

    float4 xv = *(const float4*)&X [row * 1024 + tid * 4];
    float4 cv = *(const float4*)&Cx[row * 1024 + tid * 4];
    float v0 = xv.x + cv.x, v1 = xv.y + cv.y, v2 = xv.z + cv.z, v3 = xv.w + cv.w;

    float sum  = block_reduce_sum(v0 + v1 + v2 + v3, red);
    float ssq  = block_reduce_sum(v0 * v0 + v1 * v1 + v2 * v2 + v3 * v3, red);
    float mean = sum * (1.f / 1024.f);
    float var  = ssq * (1.f / 1024.f) - mean * mean;
    float rstd = rsqrtf(var + 1e-5f);

    float4 gv = *(const float4*)&g[tid * 4];
    float4 bv = *(const float4*)&b[tid * 4];
    float4 o;
    o.x = (v0 - mean) * rstd * gv.x + bv.x;
    o.y = (v1 - mean) * rstd * gv.y + bv.y;
    o.z = (v2 - mean) * rstd * gv.z + bv.z;
    o.w = (v3 - mean) * rstd * gv.w + bv.w;
    *(float4*)&out[row * 1024 + tid * 4] = o;
}

// ---------------------------------------------------------------------------
extern "C" void kernel_launch(void* const* d_in, const int* in_sizes, int n_in,
                              void* d_out, int out_size)
{
    const float* node_fts = (const float*)d_in[0];   // (32,1024,1024)
    const float* rel      = (const float*)d_in[1];   // (32,1024,1024)
    const float* W_emb    = (const float*)d_in[2];   // (1024,1024)
    const float* b_emb    = (const float*)d_in[3];   // (1024)
    const float* Wq       = (const float*)d_in[4];   // (2,1024,512)
    const float* bq       = (const float*)d_in[5];   // (2,512)
    const float* Wk       = (const float*)d_in[6];   // (2,1024,512)
    const float* bk       = (const float*)d_in[7];   // (2,512)
    const float* Wc       = (const float*)d_in[8];   // (2,1024,1024)
    const float* ln_g     = (const float*)d_in[9];   // (2,1024)
    const float* ln_b     = (const float*)d_in[10];  // (2,1024)
    float* out = (float*)d_out;                      // (32,1024,1024)

    float *X, *Q, *K, *S, *C, *C2;
    cudaGetSymbolAddress((void**)&X,  g_X);
    cudaGetSymbolAddress((void**)&Q,  g_Q);
    cudaGetSymbolAddress((void**)&K,  g_K);
    cudaGetSymbolAddress((void**)&S,  g_S);
    cudaGetSymbolAddress((void**)&C,  g_C);
    cudaGetSymbolAddress((void**)&C2, g_C2);

    dim3 blk(256);
    const float inv_sqrt_dff = 1.0f / sqrtf((float)DFF);

    // Embedding: X = relu(NF @ W_emb + b_emb)    [32768 x 1024 x 1024]
    gemm_tc<false, true, true>
        <<<dim3(DD / BN, (int)(MTOT / BM), 1), blk>>>(
            node_fts, W_emb, b_emb, X, (int)MTOT, DD, DD, 0, 0, 0, 1.0f);

    for (int l = 0; l < 2; l++) {
        const float* Wql = Wq + (long long)l * DD * DFF;
        const float* bql = bq + (long long)l * DFF;
        const float* Wkl = Wk + (long long)l * DD * DFF;
        const float* bkl = bk + (long long)l * DFF;
        const float* Wcl = Wc + (long long)l * DD * DD;
        const float* gl  = ln_g + (long long)l * DD;
        const float* bl  = ln_b + (long long)l * DD;

        // Q = X @ Wq + bq ; K = X @ Wk + bk     [32768 x 512 x 1024]
        gemm_tc<false, false, true>
            <<<dim3(DFF / BN, (int)(MTOT / BM), 1), blk>>>(
                X, Wql, bql, Q, (int)MTOT, DFF, DD, 0, 0, 0, 1.0f);
        gemm_tc<false, false, true>
            <<<dim3(DFF / BN, (int)(MTOT / BM), 1), blk>>>(
                X, Wkl, bkl, K, (int)MTOT, DFF, DD, 0, 0, 0, 1.0f);

        // S = (Q @ K^T) / sqrt(DFF)             [32 x (1024 x 1024 x 512)]
        gemm_tc<true, false, false>
            <<<dim3(NN_ / BN, NN_ / BM, BB), blk>>>(
                Q, K, nullptr, S, NN_, NN_, DFF,
                (long long)NN_ * DFF, (long long)NN_ * DFF,
                (long long)NN_ * NN_, inv_sqrt_dff);

        // masked softmax over rows of S
        softmax_mask_kernel<<<(int)MTOT, blk>>>(S, rel);

        // C = S @ X                              [32 x (1024 x 1024 x 1024)]
        gemm_tc<false, false, false>
            <<<dim3(DD / BN, NN_ / BM, BB), blk>>>(
                S, X, nullptr, C, NN_, DD, NN_,
                (long long)NN_ * NN_, (long long)NN_ * DD,
                (long long)NN_ * DD, 1.0f);

        // C2 = C @ Wc                            [32768 x 1024 x 1024]
        gemm_tc<false, false, false>
            <<<dim3(DD / BN, (int)(MTOT / BM), 1), blk>>>(
                C, Wcl, nullptr, C2, (int)MTOT, DD, DD, 0, 0, 0, 1.0f);

        // X = LN(X + C2) * g + b   (last layer writes d_out)
        float* dst = (l == 1) ? out : X;
        add_ln_kernel<<<(int)MTOT, blk>>>(X, C2, gl, bl, dst);
    }
}

// round 3
// speedup vs baseline: 3.2263x; 1.1497x over previous
#include <cuda_runtime.h>
#include <math.h>
#include <stdint.h>

// ---------------------------------------------------------------------------
// GCNEncoder on tensor cores (tf32 mma.sync) with cp.async double buffering.
// Shapes: B=32, N=1024, D=1024, D_FF=512, L=2. All GEMM dims % 128 == 0.
// ---------------------------------------------------------------------------

#define BM 128
#define BN 128
#define BK 32
#define A_STRIDE 36     // [m][k] padded
#define B_STRIDE 136    // [k][n] padded (non-trans B)
// stage words: A = 128*36 = 4608, B = max(32*136=4352, 128*36=4608) -> 4608
#define STAGE_A_WORDS 4608
#define STAGE_B_WORDS 4608
#define STAGE_WORDS   (STAGE_A_WORDS + STAGE_B_WORDS)
#define SMEM_BYTES    (2 * STAGE_WORDS * 4)

static const int BB   = 32;
static const int NN_  = 1024;
static const int DD   = 1024;
static const int DFF  = 512;
static const long long MTOT = 32768; // B*N

// Scratch (device globals; no allocations allowed)
__device__ float g_X [32768ll * 1024];
__device__ float g_Q [32768ll * 512];
__device__ float g_K [32768ll * 512];
__device__ float g_S [32ll * 1024 * 1024];
__device__ float g_C [32768ll * 1024];
__device__ float g_C2[32768ll * 1024];

__device__ __forceinline__ uint32_t f2tf32(float x) {
    uint32_t t;
    asm("cvt.rna.tf32.f32 %0, %1;" : "=r"(t) : "f"(x));
    return t;
}

__device__ __forceinline__ void cp_async16(float* smem_ptr, const float* gmem) {
    uint32_t s = (uint32_t)__cvta_generic_to_shared(smem_ptr);
    asm volatile("cp.async.cg.shared.global [%0], [%1], 16;\n" :: "r"(s), "l"(gmem));
}
__device__ __forceinline__ void cp_commit() {
    asm volatile("cp.async.commit_group;\n" ::: "memory");
}
template <int N>
__device__ __forceinline__ void cp_wait() {
    asm volatile("cp.async.wait_group %0;\n" :: "n"(N) : "memory");
}

__device__ __forceinline__ void mma_tf32(float c[4], const uint32_t a[4],
                                         const uint32_t b[2]) {
    asm volatile(
        "mma.sync.aligned.m16n8k8.row.col.f32.tf32.tf32.f32 "
        "{%0,%1,%2,%3}, {%4,%5,%6,%7}, {%8,%9}, {%0,%1,%2,%3};\n"
        : "+f"(c[0]), "+f"(c[1]), "+f"(c[2]), "+f"(c[3])
        : "r"(a[0]), "r"(a[1]), "r"(a[2]), "r"(a[3]),
          "r"(b[0]), "r"(b[1]));
}

// ---------------------------------------------------------------------------
// Tensor-core GEMM with 2-stage cp.async pipeline.
// C = alpha * A(MxK) * B  (+bias) (+relu)
// TRANS_B=false: B is K x N row-major, staged [k][n] stride 136.
// TRANS_B=true : B is N x K row-major, staged [n][k] stride 36.
// 256 threads = 8 warps (2m x 4n); warp tile 64x32; 4x4 m16n8k8 frags.
// ---------------------------------------------------------------------------
template <bool TRANS_B, bool RELU, bool BIAS>
__global__ void __launch_bounds__(256, 2)
gemm_tc(const float* __restrict__ A, const float* __restrict__ B,
        const float* __restrict__ bias, float* __restrict__ C,
        int M, int N, int K,
        long long sA, long long sB, long long sC, float alpha)
{
    extern __shared__ float smem[];

    const int bz = blockIdx.z;
    A += (long long)bz * sA;
    B += (long long)bz * sB;
    C += (long long)bz * sC;

    const int tid  = threadIdx.x;
    const int lane = tid & 31;
    const int wid  = tid >> 5;
    const int warpM = wid >> 2;  // 0..1
    const int warpN = wid & 3;   // 0..3
    const int rowBase = blockIdx.y * BM;
    const int colBase = blockIdx.x * BN;

    // per-thread copy coordinates (4 chunks of 16B each for A and for B)
    // A tile: 128 rows x 32 floats; chunk id in [0,1024)
    const int a_r  = tid >> 1;            // used with i*... recompute below
    (void)a_r;

    float acc[4][4][4];
#pragma unroll
    for (int i = 0; i < 4; i++)
#pragma unroll
        for (int j = 0; j < 4; j++)
#pragma unroll
            for (int r = 0; r < 4; r++) acc[i][j][r] = 0.f;

    const int lq = lane >> 2;   // 0..7
    const int lr = lane & 3;    // 0..3

    const int kTiles = K / BK;

    auto issue_stage = [&](int it, int buf) {
        float* As = smem + buf * STAGE_WORDS;
        float* Bs = As + STAGE_A_WORDS;
        const int k0 = it * BK;
        // A: 1024 chunks of 4 floats
#pragma unroll
        for (int i = 0; i < 4; i++) {
            int gid = tid + i * 256;
            int r = gid >> 3;              // 0..127
            int c = (gid & 7) * 4;         // 0..28
            cp_async16(&As[r * A_STRIDE + c],
                       &A[(long long)(rowBase + r) * K + k0 + c]);
        }
        if (!TRANS_B) {
#pragma unroll
            for (int i = 0; i < 4; i++) {
                int gid = tid + i * 256;
                int r = gid >> 5;          // 0..31 (k)
                int c = (gid & 31) * 4;    // 0..124 (n)
                cp_async16(&Bs[r * B_STRIDE + c],
                           &B[(long long)(k0 + r) * N + colBase + c]);
            }
        } else {
#pragma unroll
            for (int i = 0; i < 4; i++) {
                int gid = tid + i * 256;
                int n = gid >> 3;          // 0..127
                int c = (gid & 7) * 4;     // 0..28 (k)
                cp_async16(&Bs[n * A_STRIDE + c],
                           &B[(long long)(colBase + n) * K + k0 + c]);
            }
        }
        cp_commit();
    };

    issue_stage(0, 0);

    for (int it = 0; it < kTiles; it++) {
        const int buf = it & 1;
        if (it + 1 < kTiles) {
            issue_stage(it + 1, buf ^ 1);
            cp_wait<1>();
        } else {
            cp_wait<0>();
        }
        __syncthreads();

        const float* As = smem + buf * STAGE_WORDS;
        const float* Bs = As + STAGE_A_WORDS;

#pragma unroll
        for (int ks = 0; ks < 4; ks++) {
            const int kb = ks * 8;
            uint32_t afr[4][4];
#pragma unroll
            for (int i = 0; i < 4; i++) {
                int base = (warpM * 64 + i * 16 + lq) * A_STRIDE + kb + lr;
                afr[i][0] = f2tf32(As[base]);
                afr[i][1] = f2tf32(As[base + 8 * A_STRIDE]);
                afr[i][2] = f2tf32(As[base + 4]);
                afr[i][3] = f2tf32(As[base + 8 * A_STRIDE + 4]);
            }
            uint32_t bfr[4][2];
#pragma unroll
            for (int j = 0; j < 4; j++) {
                int bcol = warpN * 32 + j * 8 + lq;
                if (!TRANS_B) {
                    bfr[j][0] = f2tf32(Bs[(kb + lr) * B_STRIDE + bcol]);
                    bfr[j][1] = f2tf32(Bs[(kb + lr + 4) * B_STRIDE + bcol]);
                } else {
                    bfr[j][0] = f2tf32(Bs[bcol * A_STRIDE + kb + lr]);
                    bfr[j][1] = f2tf32(Bs[bcol * A_STRIDE + kb + lr + 4]);
                }
            }
#pragma unroll
            for (int i = 0; i < 4; i++)
#pragma unroll
                for (int j = 0; j < 4; j++)
                    mma_tf32(acc[i][j], afr[i], bfr[j]);
        }
        __syncthreads();
    }

    // ---- epilogue
#pragma unroll
    for (int i = 0; i < 4; i++) {
        int row0 = rowBase + warpM * 64 + i * 16 + lq;
#pragma unroll
        for (int j = 0; j < 4; j++) {
            int col = colBase + warpN * 32 + j * 8 + lr * 2;
            float b0 = 0.f, b1 = 0.f;
            if (BIAS) { b0 = bias[col]; b1 = bias[col + 1]; }
            float2 v;
            v.x = acc[i][j][0] * alpha + b0;
            v.y = acc[i][j][1] * alpha + b1;
            if (RELU) { v.x = fmaxf(v.x, 0.f); v.y = fmaxf(v.y, 0.f); }
            *(float2*)&C[(long long)row0 * N + col] = v;
            v.x = acc[i][j][2] * alpha + b0;
            v.y = acc[i][j][3] * alpha + b1;
            if (RELU) { v.x = fmaxf(v.x, 0.f); v.y = fmaxf(v.y, 0.f); }
            *(float2*)&C[(long long)(row0 + 8) * N + col] = v;
        }
    }
}

// ---------------------------------------------------------------------------
// Block-wide reduction helpers (blockDim.x == 256)
// ---------------------------------------------------------------------------
__device__ __forceinline__ float block_reduce_max(float v, float* red) {
    int lane = threadIdx.x & 31, wid = threadIdx.x >> 5;
#pragma unroll
    for (int o = 16; o > 0; o >>= 1) v = fmaxf(v, __shfl_xor_sync(0xffffffffu, v, o));
    if (lane == 0) red[wid] = v;
    __syncthreads();
    if (wid == 0) {
        float x = (lane < 8) ? red[lane] : -INFINITY;
#pragma unroll
        for (int o = 4; o > 0; o >>= 1) x = fmaxf(x, __shfl_xor_sync(0xffffffffu, x, o));
        if (lane == 0) red[0] = x;
    }
    __syncthreads();
    float r = red[0];
    __syncthreads();
    return r;
}

__device__ __forceinline__ float block_reduce_sum(float v, float* red) {
    int lane = threadIdx.x & 31, wid = threadIdx.x >> 5;
#pragma unroll
    for (int o = 16; o > 0; o >>= 1) v += __shfl_xor_sync(0xffffffffu, v, o);
    if (lane == 0) red[wid] = v;
    __syncthreads();
    if (wid == 0) {
        float x = (lane < 8) ? red[lane] : 0.f;
#pragma unroll
        for (int o = 4; o > 0; o >>= 1) x += __shfl_xor_sync(0xffffffffu, x, o);
        if (lane == 0) red[0] = x;
    }
    __syncthreads();
    float r = red[0];
    __syncthreads();
    return r;
}

// ---------------------------------------------------------------------------
// Masked softmax over each 1024-wide row of S (in place). mask = (rel == 0)
// ---------------------------------------------------------------------------
__global__ void __launch_bounds__(256)
softmax_mask_kernel(float* __restrict__ S, const float* __restrict__ rel)
{
    __shared__ float red[8];
    long long row = blockIdx.x;
    float* s = S + row * 1024;
    const float* r = rel + row * 1024;
    int tid = threadIdx.x;

    float4 sv = *(const float4*)&s[tid * 4];
    float4 mv = *(const float4*)&r[tid * 4];
    float v0 = (mv.x != 0.f) ? sv.x : -INFINITY;
    float v1 = (mv.y != 0.f) ? sv.y : -INFINITY;
    float v2 = (mv.z != 0.f) ? sv.z : -INFINITY;
    float v3 = (mv.w != 0.f) ? sv.w : -INFINITY;

    float vmax = block_reduce_max(fmaxf(fmaxf(v0, v1), fmaxf(v2, v3)), red);

    float e0 = (mv.x != 0.f) ? expf(v0 - vmax) : 0.f;
    float e1 = (mv.y != 0.f) ? expf(v1 - vmax) : 0.f;
    float e2 = (mv.z != 0.f) ? expf(v2 - vmax) : 0.f;
    float e3 = (mv.w != 0.f) ? expf(v3 - vmax) : 0.f;

    float sum = block_reduce_sum(e0 + e1 + e2 + e3, red);
    float inv = (sum > 0.f) ? (1.f / sum) : 0.f;

    float4 o; o.x = e0 * inv; o.y = e1 * inv; o.z = e2 * inv; o.w = e3 * inv;
    *(float4*)&s[tid * 4] = o;
}

// ---------------------------------------------------------------------------
// out[row] = LayerNorm(X[row] + Cx[row]) * g + b   (row length 1024)
// ---------------------------------------------------------------------------
__global__ void __launch_bounds__(256)
add_ln_kernel(const float* __restrict__ X, const float* __restrict__ Cx,
              const float* __restrict__ g, const float* __restrict__ b,
              float* __restrict__ out)
{
    __shared__ float red[8];
    long long row = blockIdx.x;
    int tid = threadIdx.x;

    float4 xv = *(const float4*)&X [row * 1024 + tid * 4];
    float4 cv = *(const float4*)&Cx[row * 1024 + tid * 4];
    float v0 = xv.x + cv.x, v1 = xv.y + cv.y, v2 = xv.z + cv.z, v3 = xv.w + cv.w;

    float sum  = block_reduce_sum(v0 + v1 + v2 + v3, red);
    float ssq  = block_reduce_sum(v0 * v0 + v1 * v1 + v2 * v2 + v3 * v3, red);
    float mean = sum * (1.f / 1024.f);
    float var  = ssq * (1.f / 1024.f) - mean * mean;
    float rstd = rsqrtf(var + 1e-5f);

    float4 gv = *(const float4*)&g[tid * 4];
    float4 bv = *(const float4*)&b[tid * 4];
    float4 o;
    o.x = (v0 - mean) * rstd * gv.x + bv.x;
    o.y = (v1 - mean) * rstd * gv.y + bv.y;
    o.z = (v2 - mean) * rstd * gv.z + bv.z;
    o.w = (v3 - mean) * rstd * gv.w + bv.w;
    *(float4*)&out[row * 1024 + tid * 4] = o;
}

// ---------------------------------------------------------------------------
extern "C" void kernel_launch(void* const* d_in, const int* in_sizes, int n_in,
                              void* d_out, int out_size)
{
    const float* node_fts = (const float*)d_in[0];   // (32,1024,1024)
    const float* rel      = (const float*)d_in[1];   // (32,1024,1024)
    const float* W_emb    = (const float*)d_in[2];   // (1024,1024)
    const float* b_emb    = (const float*)d_in[3];   // (1024)
    const float* Wq       = (const float*)d_in[4];   // (2,1024,512)
    const float* bq       = (const float*)d_in[5];   // (2,512)
    const float* Wk       = (const float*)d_in[6];   // (2,1024,512)
    const float* bk       = (const float*)d_in[7];   // (2,512)
    const float* Wc       = (const float*)d_in[8];   // (2,1024,1024)
    const float* ln_g     = (const float*)d_in[9];   // (2,1024)
    const float* ln_b     = (const float*)d_in[10];  // (2,1024)
    float* out = (float*)d_out;                      // (32,1024,1024)

    float *X, *Q, *K, *S, *C, *C2;
    cudaGetSymbolAddress((void**)&X,  g_X);
    cudaGetSymbolAddress((void**)&Q,  g_Q);
    cudaGetSymbolAddress((void**)&K,  g_K);
    cudaGetSymbolAddress((void**)&S,  g_S);
    cudaGetSymbolAddress((void**)&C,  g_C);
    cudaGetSymbolAddress((void**)&C2, g_C2);

    // allow >48KB dynamic smem on all instantiations (idempotent)
    static bool attr_done = false;
    if (!attr_done) {
        cudaFuncSetAttribute(gemm_tc<false, true,  true>,
                             cudaFuncAttributeMaxDynamicSharedMemorySize, SMEM_BYTES);
        cudaFuncSetAttribute(gemm_tc<false, false, true>,
                             cudaFuncAttributeMaxDynamicSharedMemorySize, SMEM_BYTES);
        cudaFuncSetAttribute(gemm_tc<true,  false, false>,
                             cudaFuncAttributeMaxDynamicSharedMemorySize, SMEM_BYTES);
        cudaFuncSetAttribute(gemm_tc<false, false, false>,
                             cudaFuncAttributeMaxDynamicSharedMemorySize, SMEM_BYTES);
        attr_done = true;
    }

    dim3 blk(256);
    const float inv_sqrt_dff = 1.0f / sqrtf((float)DFF);

    // Embedding: X = relu(NF @ W_emb + b_emb)    [32768 x 1024 x 1024]
    gemm_tc<false, true, true>
        <<<dim3(DD / BN, (int)(MTOT / BM), 1), blk, SMEM_BYTES>>>(
            node_fts, W_emb, b_emb, X, (int)MTOT, DD, DD, 0, 0, 0, 1.0f);

    for (int l = 0; l < 2; l++) {
        const float* Wql = Wq + (long long)l * DD * DFF;
        const float* bql = bq + (long long)l * DFF;
        const float* Wkl = Wk + (long long)l * DD * DFF;
        const float* bkl = bk + (long long)l * DFF;
        const float* Wcl = Wc + (long long)l * DD * DD;
        const float* gl  = ln_g + (long long)l * DD;
        const float* bl  = ln_b + (long long)l * DD;

        // Q = X @ Wq + bq ; K = X @ Wk + bk     [32768 x 512 x 1024]
        gemm_tc<false, false, true>
            <<<dim3(DFF / BN, (int)(MTOT / BM), 1), blk, SMEM_BYTES>>>(
                X, Wql, bql, Q, (int)MTOT, DFF, DD, 0, 0, 0, 1.0f);
        gemm_tc<false, false, true>
            <<<dim3(DFF / BN, (int)(MTOT / BM), 1), blk, SMEM_BYTES>>>(
                X, Wkl, bkl, K, (int)MTOT, DFF, DD, 0, 0, 0, 1.0f);

        // S = (Q @ K^T) / sqrt(DFF)             [32 x (1024 x 1024 x 512)]
        gemm_tc<true, false, false>
            <<<dim3(NN_ / BN, NN_ / BM, BB), blk, SMEM_BYTES>>>(
                Q, K, nullptr, S, NN_, NN_, DFF,
                (long long)NN_ * DFF, (long long)NN_ * DFF,
                (long long)NN_ * NN_, inv_sqrt_dff);

        // masked softmax over rows of S
        softmax_mask_kernel<<<(int)MTOT, blk>>>(S, rel);

        // C = S @ X                              [32 x (1024 x 1024 x 1024)]
        gemm_tc<false, false, false>
            <<<dim3(DD / BN, NN_ / BM, BB), blk, SMEM_BYTES>>>(
                S, X, nullptr, C, NN_, DD, NN_,
                (long long)NN_ * NN_, (long long)NN_ * DD,
                (long long)NN_ * DD, 1.0f);

        // C2 = C @ Wc                            [32768 x 1024 x 1024]
        gemm_tc<false, false, false>
            <<<dim3(DD / BN, (int)(MTOT / BM), 1), blk, SMEM_BYTES>>>(
                C, Wcl, nullptr, C2, (int)MTOT, DD, DD, 0, 0, 0, 1.0f);

        // X = LN(X + C2) * g + b   (last layer writes d_out)
        float* dst = (l == 1) ? out : X;
        add_ln_kernel<<<(int)MTOT, blk>>>(X, C2, gl, bl, dst);
    }
}

// round 4
// speedup vs baseline: 3.4368x; 1.0653x over previous
#include <cuda_runtime.h>
#include <math.h>
#include <stdint.h>

// ---------------------------------------------------------------------------
// GCNEncoder on tensor cores (tf32 mma.sync), cp.async 3-stage pipeline,
// all tf32 conversions hoisted out of the GEMM mainloop.
// Shapes: B=32, N=1024, D=1024, D_FF=512, L=2. All GEMM dims % 128 == 0.
// ---------------------------------------------------------------------------

#define BM 128
#define BN 128
#define BK 32
#define A_STRIDE 36     // [m][k] padded
#define B_STRIDE 136    // [k][n] padded (non-trans B)
#define STAGE_A_WORDS 4608          // 128*36
#define STAGE_B_WORDS 4608          // max(32*136, 128*36)
#define STAGE_WORDS   (STAGE_A_WORDS + STAGE_B_WORDS)
#define NSTAGE 3
#define SMEM_BYTES    (NSTAGE * STAGE_WORDS * 4)

static const int BB   = 32;
static const int NN_  = 1024;
static const int DD   = 1024;
static const int DFF  = 512;
static const long long MTOT = 32768; // B*N

// Scratch (device globals; no allocations allowed)
__device__ float g_X [32768ll * 1024];
__device__ float g_Q [32768ll * 512];
__device__ float g_K [32768ll * 512];
__device__ float g_S [32ll * 1024 * 1024];
__device__ float g_C [32768ll * 1024];
__device__ float g_C2[32768ll * 1024];
__device__ float g_NF[32768ll * 1024];   // tf32-rounded node_fts
__device__ float g_W [5ll * 1024 * 1024]; // tf32-rounded weights (packed)

__device__ __forceinline__ uint32_t f2tf32(float x) {
    uint32_t t;
    asm("cvt.rna.tf32.f32 %0, %1;" : "=r"(t) : "f"(x));
    return t;
}
__device__ __forceinline__ float tf32r(float x) {
    return __uint_as_float(f2tf32(x));
}

__device__ __forceinline__ void cp_async16(float* smem_ptr, const float* gmem) {
    uint32_t s = (uint32_t)__cvta_generic_to_shared(smem_ptr);
    asm volatile("cp.async.cg.shared.global [%0], [%1], 16;\n" :: "r"(s), "l"(gmem));
}
__device__ __forceinline__ void cp_commit() {
    asm volatile("cp.async.commit_group;\n" ::: "memory");
}
template <int N>
__device__ __forceinline__ void cp_wait() {
    asm volatile("cp.async.wait_group %0;\n" :: "n"(N) : "memory");
}

__device__ __forceinline__ void mma_tf32(float c[4], const uint32_t a[4],
                                         const uint32_t b[2]) {
    asm volatile(
        "mma.sync.aligned.m16n8k8.row.col.f32.tf32.tf32.f32 "
        "{%0,%1,%2,%3}, {%4,%5,%6,%7}, {%8,%9}, {%0,%1,%2,%3};\n"
        : "+f"(c[0]), "+f"(c[1]), "+f"(c[2]), "+f"(c[3])
        : "r"(a[0]), "r"(a[1]), "r"(a[2]), "r"(a[3]),
          "r"(b[0]), "r"(b[1]));
}

// ---------------------------------------------------------------------------
// Elementwise tf32 rounding: out[i] = tf32(in[i]). n % 1024 == 0.
// ---------------------------------------------------------------------------
__global__ void __launch_bounds__(256)
tf32_round_kernel(const float* __restrict__ in, float* __restrict__ out,
                  long long n)
{
    long long i = ((long long)blockIdx.x * blockDim.x + threadIdx.x) * 4;
    if (i >= n) return;
    float4 v = *(const float4*)&in[i];
    v.x = tf32r(v.x); v.y = tf32r(v.y); v.z = tf32r(v.z); v.w = tf32r(v.w);
    *(float4*)&out[i] = v;
}

// ---------------------------------------------------------------------------
// Tensor-core GEMM, 3-stage cp.async pipeline, no cvt in mainloop
// (operands must already be tf32-rounded fp32 bit patterns).
// C = alpha * A(MxK) * B  (+bias) (+relu) (CVT_OUT: round output to tf32)
// TRANS_B=false: B is K x N row-major, staged [k][n].
// TRANS_B=true : B is N x K row-major, staged [n][k].
// 256 threads = 8 warps (2m x 4n); warp tile 64x32; 4x4 m16n8k8 frags.
// ---------------------------------------------------------------------------
template <bool TRANS_B, bool RELU, bool BIAS, bool CVT_OUT>
__global__ void __launch_bounds__(256, 2)
gemm_tc(const float* __restrict__ A, const float* __restrict__ B,
        const float* __restrict__ bias, float* __restrict__ C,
        int M, int N, int K,
        long long sA, long long sB, long long sC, float alpha)
{
    extern __shared__ float smem[];

    const int bz = blockIdx.z;
    A += (long long)bz * sA;
    B += (long long)bz * sB;
    C += (long long)bz * sC;

    const int tid  = threadIdx.x;
    const int lane = tid & 31;
    const int wid  = tid >> 5;
    const int warpM = wid >> 2;  // 0..1
    const int warpN = wid & 3;   // 0..3
    const int rowBase = blockIdx.y * BM;
    const int colBase = blockIdx.x * BN;

    float acc[4][4][4];
#pragma unroll
    for (int i = 0; i < 4; i++)
#pragma unroll
        for (int j = 0; j < 4; j++)
#pragma unroll
            for (int r = 0; r < 4; r++) acc[i][j][r] = 0.f;

    const int lq = lane >> 2;   // 0..7
    const int lr = lane & 3;    // 0..3

    const int kTiles = K / BK;

    auto issue_stage = [&](int it) {
        float* As = smem + (it % NSTAGE) * STAGE_WORDS;
        float* Bs = As + STAGE_A_WORDS;
        const int k0 = it * BK;
#pragma unroll
        for (int i = 0; i < 4; i++) {
            int gid = tid + i * 256;
            int r = gid >> 3;              // 0..127
            int c = (gid & 7) * 4;         // 0..28
            cp_async16(&As[r * A_STRIDE + c],
                       &A[(long long)(rowBase + r) * K + k0 + c]);
        }
        if (!TRANS_B) {
#pragma unroll
            for (int i = 0; i < 4; i++) {
                int gid = tid + i * 256;
                int r = gid >> 5;          // 0..31 (k)
                int c = (gid & 31) * 4;    // 0..124 (n)
                cp_async16(&Bs[r * B_STRIDE + c],
                           &B[(long long)(k0 + r) * N + colBase + c]);
            }
        } else {
#pragma unroll
            for (int i = 0; i < 4; i++) {
                int gid = tid + i * 256;
                int n = gid >> 3;          // 0..127
                int c = (gid & 7) * 4;     // 0..28 (k)
                cp_async16(&Bs[n * A_STRIDE + c],
                           &B[(long long)(colBase + n) * K + k0 + c]);
            }
        }
        cp_commit();
    };

    issue_stage(0);
    issue_stage(1);

    for (int it = 0; it < kTiles; it++) {
        if (it + 1 < kTiles) cp_wait<1>(); else cp_wait<0>();
        __syncthreads();
        if (it + 2 < kTiles) issue_stage(it + 2);

        const uint32_t* As = (const uint32_t*)(smem + (it % NSTAGE) * STAGE_WORDS);
        const uint32_t* Bs = As + STAGE_A_WORDS;

#pragma unroll
        for (int ks = 0; ks < 4; ks++) {
            const int kb = ks * 8;
            uint32_t afr[4][4];
#pragma unroll
            for (int i = 0; i < 4; i++) {
                int base = (warpM * 64 + i * 16 + lq) * A_STRIDE + kb + lr;
                afr[i][0] = As[base];
                afr[i][1] = As[base + 8 * A_STRIDE];
                afr[i][2] = As[base + 4];
                afr[i][3] = As[base + 8 * A_STRIDE + 4];
            }
            uint32_t bfr[4][2];
#pragma unroll
            for (int j = 0; j < 4; j++) {
                int bcol = warpN * 32 + j * 8 + lq;
                if (!TRANS_B) {
                    bfr[j][0] = Bs[(kb + lr) * B_STRIDE + bcol];
                    bfr[j][1] = Bs[(kb + lr + 4) * B_STRIDE + bcol];
                } else {
                    bfr[j][0] = Bs[bcol * A_STRIDE + kb + lr];
                    bfr[j][1] = Bs[bcol * A_STRIDE + kb + lr + 4];
                }
            }
#pragma unroll
            for (int i = 0; i < 4; i++)
#pragma unroll
                for (int j = 0; j < 4; j++)
                    mma_tf32(acc[i][j], afr[i], bfr[j]);
        }
    }

    // ---- epilogue
#pragma unroll
    for (int i = 0; i < 4; i++) {
        int row0 = rowBase + warpM * 64 + i * 16 + lq;
#pragma unroll
        for (int j = 0; j < 4; j++) {
            int col = colBase + warpN * 32 + j * 8 + lr * 2;
            float b0 = 0.f, b1 = 0.f;
            if (BIAS) { b0 = bias[col]; b1 = bias[col + 1]; }
            float2 v;
            v.x = acc[i][j][0] * alpha + b0;
            v.y = acc[i][j][1] * alpha + b1;
            if (RELU) { v.x = fmaxf(v.x, 0.f); v.y = fmaxf(v.y, 0.f); }
            if (CVT_OUT) { v.x = tf32r(v.x); v.y = tf32r(v.y); }
            *(float2*)&C[(long long)row0 * N + col] = v;
            v.x = acc[i][j][2] * alpha + b0;
            v.y = acc[i][j][3] * alpha + b1;
            if (RELU) { v.x = fmaxf(v.x, 0.f); v.y = fmaxf(v.y, 0.f); }
            if (CVT_OUT) { v.x = tf32r(v.x); v.y = tf32r(v.y); }
            *(float2*)&C[(long long)(row0 + 8) * N + col] = v;
        }
    }
}

// ---------------------------------------------------------------------------
// Block-wide reduction helpers (blockDim.x == 256)
// ---------------------------------------------------------------------------
__device__ __forceinline__ float block_reduce_max(float v, float* red) {
    int lane = threadIdx.x & 31, wid = threadIdx.x >> 5;
#pragma unroll
    for (int o = 16; o > 0; o >>= 1) v = fmaxf(v, __shfl_xor_sync(0xffffffffu, v, o));
    if (lane == 0) red[wid] = v;
    __syncthreads();
    if (wid == 0) {
        float x = (lane < 8) ? red[lane] : -INFINITY;
#pragma unroll
        for (int o = 4; o > 0; o >>= 1) x = fmaxf(x, __shfl_xor_sync(0xffffffffu, x, o));
        if (lane == 0) red[0] = x;
    }
    __syncthreads();
    float r = red[0];
    __syncthreads();
    return r;
}

__device__ __forceinline__ float block_reduce_sum(float v, float* red) {
    int lane = threadIdx.x & 31, wid = threadIdx.x >> 5;
#pragma unroll
    for (int o = 16; o > 0; o >>= 1) v += __shfl_xor_sync(0xffffffffu, v, o);
    if (lane == 0) red[wid] = v;
    __syncthreads();
    if (wid == 0) {
        float x = (lane < 8) ? red[lane] : 0.f;
#pragma unroll
        for (int o = 4; o > 0; o >>= 1) x += __shfl_xor_sync(0xffffffffu, x, o);
        if (lane == 0) red[0] = x;
    }
    __syncthreads();
    float r = red[0];
    __syncthreads();
    return r;
}

// ---------------------------------------------------------------------------
// Masked softmax over each 1024-wide row of S (in place). mask = (rel == 0)
// Output rounded to tf32 (consumed only by the S@X GEMM).
// ---------------------------------------------------------------------------
__global__ void __launch_bounds__(256)
softmax_mask_kernel(float* __restrict__ S, const float* __restrict__ rel)
{
    __shared__ float red[8];
    long long row = blockIdx.x;
    float* s = S + row * 1024;
    const float* r = rel + row * 1024;
    int tid = threadIdx.x;

    float4 sv = *(const float4*)&s[tid * 4];
    float4 mv = *(const float4*)&r[tid * 4];
    float v0 = (mv.x != 0.f) ? sv.x : -INFINITY;
    float v1 = (mv.y != 0.f) ? sv.y : -INFINITY;
    float v2 = (mv.z != 0.f) ? sv.z : -INFINITY;
    float v3 = (mv.w != 0.f) ? sv.w : -INFINITY;

    float vmax = block_reduce_max(fmaxf(fmaxf(v0, v1), fmaxf(v2, v3)), red);

    float e0 = (mv.x != 0.f) ? expf(v0 - vmax) : 0.f;
    float e1 = (mv.y != 0.f) ? expf(v1 - vmax) : 0.f;
    float e2 = (mv.z != 0.f) ? expf(v2 - vmax) : 0.f;
    float e3 = (mv.w != 0.f) ? expf(v3 - vmax) : 0.f;

    float sum = block_reduce_sum(e0 + e1 + e2 + e3, red);
    float inv = (sum > 0.f) ? (1.f / sum) : 0.f;

    float4 o;
    o.x = tf32r(e0 * inv); o.y = tf32r(e1 * inv);
    o.z = tf32r(e2 * inv); o.w = tf32r(e3 * inv);
    *(float4*)&s[tid * 4] = o;
}

// ---------------------------------------------------------------------------
// out[row] = LayerNorm(X[row] + Cx[row]) * g + b   (row length 1024)
// CVT: round output to tf32 (when it feeds the next layer's GEMMs).
// ---------------------------------------------------------------------------
template <bool CVT>
__global__ void __launch_bounds__(256)
add_ln_kernel(const float* __restrict__ X, const float* __restrict__ Cx,
              const float* __restrict__ g, const float* __restrict__ b,
              float* __restrict__ out)
{
    __shared__ float red[8];
    long long row = blockIdx.x;
    int tid = threadIdx.x;

    float4 xv = *(const float4*)&X [row * 1024 + tid * 4];
    float4 cv = *(const float4*)&Cx[row * 1024 + tid * 4];
    float v0 = xv.x + cv.x, v1 = xv.y + cv.y, v2 = xv.z + cv.z, v3 = xv.w + cv.w;

    float sum  = block_reduce_sum(v0 + v1 + v2 + v3, red);
    float ssq  = block_reduce_sum(v0 * v0 + v1 * v1 + v2 * v2 + v3 * v3, red);
    float mean = sum * (1.f / 1024.f);
    float var  = ssq * (1.f / 1024.f) - mean * mean;
    float rstd = rsqrtf(var + 1e-5f);

    float4 gv = *(const float4*)&g[tid * 4];
    float4 bv = *(const float4*)&b[tid * 4];
    float4 o;
    o.x = (v0 - mean) * rstd * gv.x + bv.x;
    o.y = (v1 - mean) * rstd * gv.y + bv.y;
    o.z = (v2 - mean) * rstd * gv.z + bv.z;
    o.w = (v3 - mean) * rstd * gv.w + bv.w;
    if (CVT) { o.x = tf32r(o.x); o.y = tf32r(o.y); o.z = tf32r(o.z); o.w = tf32r(o.w); }
    *(float4*)&out[row * 1024 + tid * 4] = o;
}

// ---------------------------------------------------------------------------
extern "C" void kernel_launch(void* const* d_in, const int* in_sizes, int n_in,
                              void* d_out, int out_size)
{
    const float* node_fts = (const float*)d_in[0];   // (32,1024,1024)
    const float* rel      = (const float*)d_in[1];   // (32,1024,1024)
    const float* W_emb    = (const float*)d_in[2];   // (1024,1024)
    const float* b_emb    = (const float*)d_in[3];   // (1024)
    const float* Wq       = (const float*)d_in[4];   // (2,1024,512)
    const float* bq       = (const float*)d_in[5];   // (2,512)
    const float* Wk       = (const float*)d_in[6];   // (2,1024,512)
    const float* bk       = (const float*)d_in[7];   // (2,512)
    const float* Wc       = (const float*)d_in[8];   // (2,1024,1024)
    const float* ln_g     = (const float*)d_in[9];   // (2,1024)
    const float* ln_b     = (const float*)d_in[10];  // (2,1024)
    float* out = (float*)d_out;                      // (32,1024,1024)

    float *X, *Q, *K, *S, *C, *C2, *NF, *W;
    cudaGetSymbolAddress((void**)&X,  g_X);
    cudaGetSymbolAddress((void**)&Q,  g_Q);
    cudaGetSymbolAddress((void**)&K,  g_K);
    cudaGetSymbolAddress((void**)&S,  g_S);
    cudaGetSymbolAddress((void**)&C,  g_C);
    cudaGetSymbolAddress((void**)&C2, g_C2);
    cudaGetSymbolAddress((void**)&NF, g_NF);
    cudaGetSymbolAddress((void**)&W,  g_W);

    static bool attr_done = false;
    if (!attr_done) {
        cudaFuncSetAttribute(gemm_tc<false, true,  true,  true >,
                             cudaFuncAttributeMaxDynamicSharedMemorySize, SMEM_BYTES);
        cudaFuncSetAttribute(gemm_tc<false, false, true,  true >,
                             cudaFuncAttributeMaxDynamicSharedMemorySize, SMEM_BYTES);
        cudaFuncSetAttribute(gemm_tc<true,  false, false, false>,
                             cudaFuncAttributeMaxDynamicSharedMemorySize, SMEM_BYTES);
        cudaFuncSetAttribute(gemm_tc<false, false, false, true >,
                             cudaFuncAttributeMaxDynamicSharedMemorySize, SMEM_BYTES);
        cudaFuncSetAttribute(gemm_tc<false, false, false, false>,
                             cudaFuncAttributeMaxDynamicSharedMemorySize, SMEM_BYTES);
        attr_done = true;
    }

    dim3 blk(256);
    const float inv_sqrt_dff = 1.0f / sqrtf((float)DFF);

    // Packed tf32 weight buffer offsets (floats)
    float* Wemb_t = W;                       // 1M
    float* Wq_t   = W + 1024ll * 1024;       // 1M (both layers)
    float* Wk_t   = W + 2048ll * 1024;       // 1M
    float* Wc_t   = W + 3072ll * 1024;       // 2M

    // Pre-round inputs & weights to tf32
    tf32_round_kernel<<<(int)(MTOT * DD / 4 / 256), blk>>>(node_fts, NF, MTOT * DD);
    tf32_round_kernel<<<1024, blk>>>(W_emb, Wemb_t, 1024ll * 1024);
    tf32_round_kernel<<<1024, blk>>>(Wq, Wq_t, 2ll * 1024 * 512);
    tf32_round_kernel<<<1024, blk>>>(Wk, Wk_t, 2ll * 1024 * 512);
    tf32_round_kernel<<<2048, blk>>>(Wc, Wc_t, 2ll * 1024 * 1024);

    // Embedding: X = relu(NF @ W_emb + b_emb)    [32768 x 1024 x 1024]
    gemm_tc<false, true, true, true>
        <<<dim3(DD / BN, (int)(MTOT / BM), 1), blk, SMEM_BYTES>>>(
            NF, Wemb_t, b_emb, X, (int)MTOT, DD, DD, 0, 0, 0, 1.0f);

    for (int l = 0; l < 2; l++) {
        const float* Wql = Wq_t + (long long)l * DD * DFF;
        const float* bql = bq + (long long)l * DFF;
        const float* Wkl = Wk_t + (long long)l * DD * DFF;
        const float* bkl = bk + (long long)l * DFF;
        const float* Wcl = Wc_t + (long long)l * DD * DD;
        const float* gl  = ln_g + (long long)l * DD;
        const float* bl  = ln_b + (long long)l * DD;

        // Q = X @ Wq + bq ; K = X @ Wk + bk     [32768 x 512 x 1024]
        gemm_tc<false, false, true, true>
            <<<dim3(DFF / BN, (int)(MTOT / BM), 1), blk, SMEM_BYTES>>>(
                X, Wql, bql, Q, (int)MTOT, DFF, DD, 0, 0, 0, 1.0f);
        gemm_tc<false, false, true, true>
            <<<dim3(DFF / BN, (int)(MTOT / BM), 1), blk, SMEM_BYTES>>>(
                X, Wkl, bkl, K, (int)MTOT, DFF, DD, 0, 0, 0, 1.0f);

        // S = (Q @ K^T) / sqrt(DFF)             [32 x (1024 x 1024 x 512)]
        gemm_tc<true, false, false, false>
            <<<dim3(NN_ / BN, NN_ / BM, BB), blk, SMEM_BYTES>>>(
                Q, K, nullptr, S, NN_, NN_, DFF,
                (long long)NN_ * DFF, (long long)NN_ * DFF,
                (long long)NN_ * NN_, inv_sqrt_dff);

        // masked softmax over rows of S (tf32-rounded output)
        softmax_mask_kernel<<<(int)MTOT, blk>>>(S, rel);

        // C = S @ X                              [32 x (1024 x 1024 x 1024)]
        gemm_tc<false, false, false, true>
            <<<dim3(DD / BN, NN_ / BM, BB), blk, SMEM_BYTES>>>(
                S, X, nullptr, C, NN_, DD, NN_,
                (long long)NN_ * NN_, (long long)NN_ * DD,
                (long long)NN_ * DD, 1.0f);

        // C2 = C @ Wc                            [32768 x 1024 x 1024]
        gemm_tc<false, false, false, false>
            <<<dim3(DD / BN, (int)(MTOT / BM), 1), blk, SMEM_BYTES>>>(
                C, Wcl, nullptr, C2, (int)MTOT, DD, DD, 0, 0, 0, 1.0f);

        // X = LN(X + C2) * g + b   (layer 0: tf32-rounded; layer 1 -> d_out fp32)
        if (l == 0) add_ln_kernel<true ><<<(int)MTOT, blk>>>(X, C2, gl, bl, X);
        else        add_ln_kernel<false><<<(int)MTOT, blk>>>(X, C2, gl, bl, out);
    }
}

// round 6
// speedup vs baseline: 3.4661x; 1.0085x over previous
#include <cuda_runtime.h>
#include <math.h>
#include <stdint.h>

// ---------------------------------------------------------------------------
// GCNEncoder on tensor cores (tf32 mma.sync), cp.async 3-stage pipeline.
// Block tile 128(M) x 256(N) x 32(K); 8 warps (2m x 4n); warp tile 64x64.
// All tf32 conversions hoisted out of the GEMM mainloop.
// Shapes: B=32, N=1024, D=1024, D_FF=512, L=2.
// ---------------------------------------------------------------------------

#define BM 128
#define BN 256
#define BK 32
#define A_STRIDE 36     // [m][k] padded
#define B_STRIDE 264    // [k][n] padded (non-trans B)
#define STAGE_A_WORDS 4608           // 128*36
#define STAGE_B_WORDS 9216           // max(32*264=8448, 256*36=9216)
#define STAGE_WORDS   (STAGE_A_WORDS + STAGE_B_WORDS)
#define NSTAGE 3
#define SMEM_BYTES    (NSTAGE * STAGE_WORDS * 4)   // 165,888 B

static const int BB   = 32;
static const int NN_  = 1024;
static const int DD   = 1024;
static const int DFF  = 512;
static const long long MTOT = 32768; // B*N

// Scratch (device globals; no allocations allowed)
__device__ float g_X [32768ll * 1024];
__device__ float g_Q [32768ll * 512];
__device__ float g_K [32768ll * 512];
__device__ float g_S [32ll * 1024 * 1024];
__device__ float g_C [32768ll * 1024];
__device__ float g_C2[32768ll * 1024];
__device__ float g_NF[32768ll * 1024];    // tf32-rounded node_fts
__device__ float g_W [5ll * 1024 * 1024]; // tf32-rounded weights (packed)

__device__ __forceinline__ uint32_t f2tf32(float x) {
    uint32_t t;
    asm("cvt.rna.tf32.f32 %0, %1;" : "=r"(t) : "f"(x));
    return t;
}
__device__ __forceinline__ float tf32r(float x) { return __uint_as_float(f2tf32(x)); }

__device__ __forceinline__ void cp_async16(float* smem_ptr, const float* gmem) {
    uint32_t s = (uint32_t)__cvta_generic_to_shared(smem_ptr);
    asm volatile("cp.async.cg.shared.global [%0], [%1], 16;\n" :: "r"(s), "l"(gmem));
}
__device__ __forceinline__ void cp_commit() {
    asm volatile("cp.async.commit_group;\n" ::: "memory");
}
template <int N>
__device__ __forceinline__ void cp_wait() {
    asm volatile("cp.async.wait_group %0;\n" :: "n"(N) : "memory");
}

__device__ __forceinline__ void mma_tf32(float c[4], const uint32_t a[4],
                                         const uint32_t b[2]) {
    asm volatile(
        "mma.sync.aligned.m16n8k8.row.col.f32.tf32.tf32.f32 "
        "{%0,%1,%2,%3}, {%4,%5,%6,%7}, {%8,%9}, {%0,%1,%2,%3};\n"
        : "+f"(c[0]), "+f"(c[1]), "+f"(c[2]), "+f"(c[3])
        : "r"(a[0]), "r"(a[1]), "r"(a[2]), "r"(a[3]),
          "r"(b[0]), "r"(b[1]));
}

// ---------------------------------------------------------------------------
// Elementwise tf32 rounding: out[i] = tf32(in[i]). n % 1024 == 0.
// ---------------------------------------------------------------------------
__global__ void __launch_bounds__(256)
tf32_round_kernel(const float* __restrict__ in, float* __restrict__ out,
                  long long n)
{
    long long i = ((long long)blockIdx.x * blockDim.x + threadIdx.x) * 4;
    if (i >= n) return;
    float4 v = *(const float4*)&in[i];
    v.x = tf32r(v.x); v.y = tf32r(v.y); v.z = tf32r(v.z); v.w = tf32r(v.w);
    *(float4*)&out[i] = v;
}

// ---------------------------------------------------------------------------
// Tensor-core GEMM, 3-stage cp.async pipeline, no cvt in mainloop
// (operands must already be tf32-rounded fp32 bit patterns).
// C = alpha * A(MxK) * B  (+bias) (+relu) (CVT_OUT: round output to tf32)
// TRANS_B=false: B is K x N row-major, staged [k][n] stride 264.
// TRANS_B=true : B is N x K row-major, staged [n][k] stride 36.
// 256 threads = 8 warps (2m x 4n); warp tile 64x64; 4x8 m16n8k8 frags.
// ---------------------------------------------------------------------------
template <bool TRANS_B, bool RELU, bool BIAS, bool CVT_OUT>
__global__ void __launch_bounds__(256, 1)
gemm_tc(const float* __restrict__ A, const float* __restrict__ B,
        const float* __restrict__ bias, float* __restrict__ C,
        int M, int N, int K,
        long long sA, long long sB, long long sC, float alpha)
{
    extern __shared__ float smem[];

    const int bz = blockIdx.z;
    A += (long long)bz * sA;
    B += (long long)bz * sB;
    C += (long long)bz * sC;

    const int tid  = threadIdx.x;
    const int lane = tid & 31;
    const int wid  = tid >> 5;
    const int warpM = wid >> 2;  // 0..1
    const int warpN = wid & 3;   // 0..3
    const int rowBase = blockIdx.y * BM;
    const int colBase = blockIdx.x * BN;

    float acc[4][8][4];
#pragma unroll
    for (int i = 0; i < 4; i++)
#pragma unroll
        for (int j = 0; j < 8; j++)
#pragma unroll
            for (int r = 0; r < 4; r++) acc[i][j][r] = 0.f;

    const int lq = lane >> 2;   // 0..7
    const int lr = lane & 3;    // 0..3

    const int kTiles = K / BK;

    auto issue_stage = [&](int it) {
        float* As = smem + (it % NSTAGE) * STAGE_WORDS;
        float* Bs = As + STAGE_A_WORDS;
        const int k0 = it * BK;
        // A tile: 128 x 32 floats = 1024 chunks of 16B
#pragma unroll
        for (int i = 0; i < 4; i++) {
            int gid = tid + i * 256;
            int r = gid >> 3;              // 0..127
            int c = (gid & 7) * 4;         // 0..28
            cp_async16(&As[r * A_STRIDE + c],
                       &A[(rowBase + r) * K + k0 + c]);
        }
        if (!TRANS_B) {
            // B tile: 32 x 256 floats = 2048 chunks
#pragma unroll
            for (int i = 0; i < 8; i++) {
                int gid = tid + i * 256;
                int r = gid >> 6;          // 0..31 (k)
                int c = (gid & 63) * 4;    // 0..252 (n)
                cp_async16(&Bs[r * B_STRIDE + c],
                           &B[(k0 + r) * N + colBase + c]);
            }
        } else {
            // B tile: 256 n-rows x 32 k = 2048 chunks, staged [n][k]
#pragma unroll
            for (int i = 0; i < 8; i++) {
                int gid = tid + i * 256;
                int n = gid >> 3;          // 0..255
                int c = (gid & 7) * 4;     // 0..28 (k)
                cp_async16(&Bs[n * A_STRIDE + c],
                           &B[(colBase + n) * K + k0 + c]);
            }
        }
        cp_commit();
    };

    issue_stage(0);
    issue_stage(1);

    for (int it = 0; it < kTiles; it++) {
        if (it + 1 < kTiles) cp_wait<1>(); else cp_wait<0>();
        __syncthreads();
        if (it + 2 < kTiles) issue_stage(it + 2);

        const uint32_t* As = (const uint32_t*)(smem + (it % NSTAGE) * STAGE_WORDS);
        const uint32_t* Bs = As + STAGE_A_WORDS;

#pragma unroll
        for (int ks = 0; ks < 4; ks++) {
            const int kb = ks * 8;
            uint32_t afr[4][4];
#pragma unroll
            for (int i = 0; i < 4; i++) {
                int base = (warpM * 64 + i * 16 + lq) * A_STRIDE + kb + lr;
                afr[i][0] = As[base];
                afr[i][1] = As[base + 8 * A_STRIDE];
                afr[i][2] = As[base + 4];
                afr[i][3] = As[base + 8 * A_STRIDE + 4];
            }
            uint32_t bfr[8][2];
#pragma unroll
            for (int j = 0; j < 8; j++) {
                int bcol = warpN * 64 + j * 8 + lq;
                if (!TRANS_B) {
                    bfr[j][0] = Bs[(kb + lr) * B_STRIDE + bcol];
                    bfr[j][1] = Bs[(kb + lr + 4) * B_STRIDE + bcol];
                } else {
                    bfr[j][0] = Bs[bcol * A_STRIDE + kb + lr];
                    bfr[j][1] = Bs[bcol * A_STRIDE + kb + lr + 4];
                }
            }
#pragma unroll
            for (int i = 0; i < 4; i++)
#pragma unroll
                for (int j = 0; j < 8; j++)
                    mma_tf32(acc[i][j], afr[i], bfr[j]);
        }
    }

    // ---- epilogue
#pragma unroll
    for (int i = 0; i < 4; i++) {
        int row0 = rowBase + warpM * 64 + i * 16 + lq;
#pragma unroll
        for (int j = 0; j < 8; j++) {
            int col = colBase + warpN * 64 + j * 8 + lr * 2;
            float b0 = 0.f, b1 = 0.f;
            if (BIAS) { b0 = bias[col]; b1 = bias[col + 1]; }
            float2 v;
            v.x = acc[i][j][0] * alpha + b0;
            v.y = acc[i][j][1] * alpha + b1;
            if (RELU) { v.x = fmaxf(v.x, 0.f); v.y = fmaxf(v.y, 0.f); }
            if (CVT_OUT) { v.x = tf32r(v.x); v.y = tf32r(v.y); }
            *(float2*)&C[(long long)row0 * N + col] = v;
            v.x = acc[i][j][2] * alpha + b0;
            v.y = acc[i][j][3] * alpha + b1;
            if (RELU) { v.x = fmaxf(v.x, 0.f); v.y = fmaxf(v.y, 0.f); }
            if (CVT_OUT) { v.x = tf32r(v.x); v.y = tf32r(v.y); }
            *(float2*)&C[(long long)(row0 + 8) * N + col] = v;
        }
    }
}

// ---------------------------------------------------------------------------
// Block-wide reduction helpers (blockDim.x == 256)
// ---------------------------------------------------------------------------
__device__ __forceinline__ float block_reduce_max(float v, float* red) {
    int lane = threadIdx.x & 31, wid = threadIdx.x >> 5;
#pragma unroll
    for (int o = 16; o > 0; o >>= 1) v = fmaxf(v, __shfl_xor_sync(0xffffffffu, v, o));
    if (lane == 0) red[wid] = v;
    __syncthreads();
    if (wid == 0) {
        float x = (lane < 8) ? red[lane] : -INFINITY;
#pragma unroll
        for (int o = 4; o > 0; o >>= 1) x = fmaxf(x, __shfl_xor_sync(0xffffffffu, x, o));
        if (lane == 0) red[0] = x;
    }
    __syncthreads();
    float r = red[0];
    __syncthreads();
    return r;
}

__device__ __forceinline__ float block_reduce_sum(float v, float* red) {
    int lane = threadIdx.x & 31, wid = threadIdx.x >> 5;
#pragma unroll
    for (int o = 16; o > 0; o >>= 1) v += __shfl_xor_sync(0xffffffffu, v, o);
    if (lane == 0) red[wid] = v;
    __syncthreads();
    if (wid == 0) {
        float x = (lane < 8) ? red[lane] : 0.f;
#pragma unroll
        for (int o = 4; o > 0; o >>= 1) x += __shfl_xor_sync(0xffffffffu, x, o);
        if (lane == 0) red[0] = x;
    }
    __syncthreads();
    float r = red[0];
    __syncthreads();
    return r;
}

// ---------------------------------------------------------------------------
// Masked softmax over each 1024-wide row of S (in place). mask = (rel == 0)
// Output rounded to tf32 (consumed only by the S@X GEMM).
// ---------------------------------------------------------------------------
__global__ void __launch_bounds__(256)
softmax_mask_kernel(float* __restrict__ S, const float* __restrict__ rel)
{
    __shared__ float red[8];
    long long row = blockIdx.x;
    float* s = S + row * 1024;
    const float* r = rel + row * 1024;
    int tid = threadIdx.x;

    float4 sv = *(const float4*)&s[tid * 4];
    float4 mv = *(const float4*)&r[tid * 4];
    float v0 = (mv.x != 0.f) ? sv.x : -INFINITY;
    float v1 = (mv.y != 0.f) ? sv.y : -INFINITY;
    float v2 = (mv.z != 0.f) ? sv.z : -INFINITY;
    float v3 = (mv.w != 0.f) ? sv.w : -INFINITY;

    float vmax = block_reduce_max(fmaxf(fmaxf(v0, v1), fmaxf(v2, v3)), red);

    float e0 = (mv.x != 0.f) ? expf(v0 - vmax) : 0.f;
    float e1 = (mv.y != 0.f) ? expf(v1 - vmax) : 0.f;
    float e2 = (mv.z != 0.f) ? expf(v2 - vmax) : 0.f;
    float e3 = (mv.w != 0.f) ? expf(v3 - vmax) : 0.f;

    float sum = block_reduce_sum(e0 + e1 + e2 + e3, red);
    float inv = (sum > 0.f) ? (1.f / sum) : 0.f;

    float4 o;
    o.x = tf32r(e0 * inv); o.y = tf32r(e1 * inv);
    o.z = tf32r(e2 * inv); o.w = tf32r(e3 * inv);
    *(float4*)&s[tid * 4] = o;
}

// ---------------------------------------------------------------------------
// out[row] = LayerNorm(X[row] + Cx[row]) * g + b   (row length 1024)
// CVT: round output to tf32 (when it feeds the next layer's GEMMs).
// ---------------------------------------------------------------------------
template <bool CVT>
__global__ void __launch_bounds__(256)
add_ln_kernel(const float* __restrict__ X, const float* __restrict__ Cx,
              const float* __restrict__ g, const float* __restrict__ b,
              float* __restrict__ out)
{
    __shared__ float red[8];
    long long row = blockIdx.x;
    int tid = threadIdx.x;

    float4 xv = *(const float4*)&X [row * 1024 + tid * 4];
    float4 cv = *(const float4*)&Cx[row * 1024 + tid * 4];
    float v0 = xv.x + cv.x, v1 = xv.y + cv.y, v2 = xv.z + cv.z, v3 = xv.w + cv.w;

    float sum  = block_reduce_sum(v0 + v1 + v2 + v3, red);
    float ssq  = block_reduce_sum(v0 * v0 + v1 * v1 + v2 * v2 + v3 * v3, red);
    float mean = sum * (1.f / 1024.f);
    float var  = ssq * (1.f / 1024.f) - mean * mean;
    float rstd = rsqrtf(var + 1e-5f);

    float4 gv = *(const float4*)&g[tid * 4];
    float4 bv = *(const float4*)&b[tid * 4];
    float4 o;
    o.x = (v0 - mean) * rstd * gv.x + bv.x;
    o.y = (v1 - mean) * rstd * gv.y + bv.y;
    o.z = (v2 - mean) * rstd * gv.z + bv.z;
    o.w = (v3 - mean) * rstd * gv.w + bv.w;
    if (CVT) { o.x = tf32r(o.x); o.y = tf32r(o.y); o.z = tf32r(o.z); o.w = tf32r(o.w); }
    *(float4*)&out[row * 1024 + tid * 4] = o;
}

// ---------------------------------------------------------------------------
extern "C" void kernel_launch(void* const* d_in, const int* in_sizes, int n_in,
                              void* d_out, int out_size)
{
    const float* node_fts = (const float*)d_in[0];   // (32,1024,1024)
    const float* rel      = (const float*)d_in[1];   // (32,1024,1024)
    const float* W_emb    = (const float*)d_in[2];   // (1024,1024)
    const float* b_emb    = (const float*)d_in[3];   // (1024)
    const float* Wq       = (const float*)d_in[4];   // (2,1024,512)
    const float* bq       = (const float*)d_in[5];   // (2,512)
    const float* Wk       = (const float*)d_in[6];   // (2,1024,512)
    const float* bk       = (const float*)d_in[7];   // (2,512)
    const float* Wc       = (const float*)d_in[8];   // (2,1024,1024)
    const float* ln_g     = (const float*)d_in[9];   // (2,1024)
    const float* ln_b     = (const float*)d_in[10];  // (2,1024)
    float* out = (float*)d_out;                      // (32,1024,1024)

    float *X, *Q, *K, *S, *C, *C2, *NF, *W;
    cudaGetSymbolAddress((void**)&X,  g_X);
    cudaGetSymbolAddress((void**)&Q,  g_Q);
    cudaGetSymbolAddress((void**)&K,  g_K);
    cudaGetSymbolAddress((void**)&S,  g_S);
    cudaGetSymbolAddress((void**)&C,  g_C);
    cudaGetSymbolAddress((void**)&C2, g_C2);
    cudaGetSymbolAddress((void**)&NF, g_NF);
    cudaGetSymbolAddress((void**)&W,  g_W);

    static bool attr_done = false;
    if (!attr_done) {
        cudaFuncSetAttribute(gemm_tc<false, true,  true,  true >,
                             cudaFuncAttributeMaxDynamicSharedMemorySize, SMEM_BYTES);
        cudaFuncSetAttribute(gemm_tc<false, false, true,  true >,
                             cudaFuncAttributeMaxDynamicSharedMemorySize, SMEM_BYTES);
        cudaFuncSetAttribute(gemm_tc<true,  false, false, false>,
                             cudaFuncAttributeMaxDynamicSharedMemorySize, SMEM_BYTES);
        cudaFuncSetAttribute(gemm_tc<false, false, false, true >,
                             cudaFuncAttributeMaxDynamicSharedMemorySize, SMEM_BYTES);
        cudaFuncSetAttribute(gemm_tc<false, false, false, false>,
                             cudaFuncAttributeMaxDynamicSharedMemorySize, SMEM_BYTES);
        attr_done = true;
    }

    dim3 blk(256);
    const float inv_sqrt_dff = 1.0f / sqrtf((float)DFF);

    // Packed tf32 weight buffer offsets (floats)
    float* Wemb_t = W;                       // 1M
    float* Wq_t   = W + 1024ll * 1024;       // 1M (both layers)
    float* Wk_t   = W + 2048ll * 1024;       // 1M
    float* Wc_t   = W + 3072ll * 1024;       // 2M

    // Pre-round inputs & weights to tf32
    tf32_round_kernel<<<(int)(MTOT * DD / 1024), blk>>>(node_fts, NF, MTOT * DD);
    tf32_round_kernel<<<1024, blk>>>(W_emb, Wemb_t, 1024ll * 1024);
    tf32_round_kernel<<<1024, blk>>>(Wq, Wq_t, 2ll * 1024 * 512);
    tf32_round_kernel<<<1024, blk>>>(Wk, Wk_t, 2ll * 1024 * 512);
    tf32_round_kernel<<<2048, blk>>>(Wc, Wc_t, 2ll * 1024 * 1024);

    // Embedding: X = tf32(relu(NF @ W_emb + b_emb))   [32768 x 1024 x 1024]
    gemm_tc<false, true, true, true>
        <<<dim3(DD / BN, (int)(MTOT / BM), 1), blk, SMEM_BYTES>>>(
            NF, Wemb_t, b_emb, X, (int)MTOT, DD, DD, 0, 0, 0, 1.0f);

    for (int l = 0; l < 2; l++) {
        const float* Wql = Wq_t + (long long)l * DD * DFF;
        const float* bql = bq + (long long)l * DFF;
        const float* Wkl = Wk_t + (long long)l * DD * DFF;
        const float* bkl = bk + (long long)l * DFF;
        const float* Wcl = Wc_t + (long long)l * DD * DD;
        const float* gl  = ln_g + (long long)l * DD;
        const float* bl  = ln_b + (long long)l * DD;

        // Q = tf32(X @ Wq + bq); K likewise     [32768 x 512 x 1024]
        gemm_tc<false, false, true, true>
            <<<dim3(DFF / BN, (int)(MTOT / BM), 1), blk, SMEM_BYTES>>>(
                X, Wql, bql, Q, (int)MTOT, DFF, DD, 0, 0, 0, 1.0f);
        gemm_tc<false, false, true, true>
            <<<dim3(DFF / BN, (int)(MTOT / BM), 1), blk, SMEM_BYTES>>>(
                X, Wkl, bkl, K, (int)MTOT, DFF, DD, 0, 0, 0, 1.0f);

        // S = (Q @ K^T) / sqrt(DFF)             [32 x (1024 x 1024 x 512)]
        gemm_tc<true, false, false, false>
            <<<dim3(NN_ / BN, NN_ / BM, BB), blk, SMEM_BYTES>>>(
                Q, K, nullptr, S, NN_, NN_, DFF,
                (long long)NN_ * DFF, (long long)NN_ * DFF,
                (long long)NN_ * NN_, inv_sqrt_dff);

        // masked softmax over rows of S (tf32-rounded output)
        softmax_mask_kernel<<<(int)MTOT, blk>>>(S, rel);

        // C = tf32(S @ X)                        [32 x (1024 x 1024 x 1024)]
        gemm_tc<false, false, false, true>
            <<<dim3(DD / BN, NN_ / BM, BB), blk, SMEM_BYTES>>>(
                S, X, nullptr, C, NN_, DD, NN_,
                (long long)NN_ * NN_, (long long)NN_ * DD,
                (long long)NN_ * DD, 1.0f);

        // C2 = C @ Wc                            [32768 x 1024 x 1024]
        gemm_tc<false, false, false, false>
            <<<dim3(DD / BN, (int)(MTOT / BM), 1), blk, SMEM_BYTES>>>(
                C, Wcl, nullptr, C2, (int)MTOT, DD, DD, 0, 0, 0, 1.0f);

        // X = LN(X + C2) * g + b  (layer 0: tf32-rounded; layer 1 -> d_out fp32)
        if (l == 0) add_ln_kernel<true ><<<(int)MTOT, blk>>>(X, C2, gl, bl, X);
        else        add_ln_kernel<false><<<(int)MTOT, blk>>>(X, C2, gl, bl, out);
    }
}